// round 15
// baseline (speedup 1.0000x reference)
#include <cuda_runtime.h>

// HandGraphConvNet fused: 2-layer GCN + BN(eval) + relu + residual, fp32.
//   Y  = A @ X            (sparse A: wrist=6 nnz, all other joints <=3)
//   H  = relu(Y @ W1' + beta1')      (never materialized)
//   S2 = H @ W2'
//   out = A @ S2 + beta2' + x
// R12: SPB=96 (3 samples/lane x 3 joints/warp = 9 units/thread), channel
// loop split in two register passes (5+4) to stay ~70 live regs. Grid=342
// blocks <= 444 resident slots (3/SM) -> single wave, no tail.
// Packed relu: relu(h)*w == (h + (h & 0x7fffffff)) * (w/2), 1/2 pre-folded.

#define NJ 21
#define HDIM 42
#define HIDDEN 64
#define SPB 96                 // samples per block (3 per lane)
#define NTHREADS 224           // 7 warps
#define BN_EPS 1e-5f

typedef unsigned long long ull;

__constant__ int c_nbr[NJ * 6] = {
    0,1,5,9,13,17,
    0,1,2,0,0,0, 1,2,3,0,0,0, 2,3,4,0,0,0, 3,4,0,0,0,0,
    0,5,6,0,0,0, 5,6,7,0,0,0, 6,7,8,0,0,0, 7,8,0,0,0,0,
    0,9,10,0,0,0, 9,10,11,0,0,0, 10,11,12,0,0,0, 11,12,0,0,0,0,
    0,13,14,0,0,0, 13,14,15,0,0,0, 14,15,16,0,0,0, 15,16,0,0,0,0,
    0,17,18,0,0,0, 17,18,19,0,0,0, 18,19,20,0,0,0, 19,20,0,0,0,0};
__constant__ int c_cnt[NJ] = {6,3,3,3,2,3,3,3,2,3,3,3,2,3,3,3,2,3,3,3,2};

__device__ __forceinline__ ull pk2(float lo, float hi) {
    ull r; asm("mov.b64 %0, {%1, %2};" : "=l"(r) : "f"(lo), "f"(hi)); return r;
}
__device__ __forceinline__ void upk2(ull v, float& lo, float& hi) {
    asm("mov.b64 {%0, %1}, %2;" : "=f"(lo), "=f"(hi) : "l"(v));
}
__device__ __forceinline__ ull ffma2(ull a, ull b, ull c) {
    ull d; asm("fma.rn.f32x2 %0, %1, %2, %3;" : "=l"(d) : "l"(a), "l"(b), "l"(c)); return d;
}
__device__ __forceinline__ ull fadd2(ull a, ull b) {
    ull d; asm("add.rn.f32x2 %0, %1, %2;" : "=l"(d) : "l"(a), "l"(b)); return d;
}

// one register pass over NU consecutive units starting at TOFF.
// unit u <-> (k = u/3 sample slot, jj = u%3 joint-in-warp)
template<int NU, int TOFF>
__device__ __forceinline__ void channel_pass(const ull* __restrict__ ypk,
                                             const ulonglong2* __restrict__ cap,
                                             const ull* __restrict__ ccp,
                                             const ulonglong2* __restrict__ cbp,
                                             float* __restrict__ s2s,
                                             int lane, int w)
{
    const ull ABSMASK = 0x7FFFFFFF7FFFFFFFULL;
    ull y0d[NU], y1d[NU], a0[NU], a1[NU];
    #pragma unroll
    for (int t = 0; t < NU; ++t) {
        float lo, hi; upk2(ypk[TOFF + t], lo, hi);
        y0d[t] = pk2(lo, lo);
        y1d[t] = pk2(hi, hi);
        a0[t] = 0ULL; a1[t] = 0ULL;
    }
    #pragma unroll
    for (int cp = 0; cp < 32; ++cp) {
        ulonglong2 wa = cap[cp];      // LDS.128 broadcast
        ull        bp = ccp[cp];      // LDS.64
        ulonglong2 wb = cbp[cp];      // LDS.128 (pre-scaled by 1/2)
        #pragma unroll
        for (int t = 0; t < NU; ++t) {
            ull h  = ffma2(y0d[t], wa.x, ffma2(y1d[t], wa.y, bp));
            ull hr = fadd2(h, h & ABSMASK);        // 2*relu(h), packed
            a0[t] = ffma2(hr, wb.x, a0[t]);
            a1[t] = ffma2(hr, wb.y, a1[t]);
        }
    }
    #pragma unroll
    for (int t = 0; t < NU; ++t) {
        const int u = TOFF + t, k = u / 3, jj = u % 3;
        float p, q, r, s;
        upk2(a0[t], p, q);
        upk2(a1[t], r, s);
        *(float2*)(s2s + (lane + 32 * k) * HDIM + 2 * (3 * w + jj)) =
            make_float2(p + q, r + s);
    }
}

__global__ __launch_bounds__(NTHREADS, 3)
void hand_gcn_kernel(const float* __restrict__ x,  const float* __restrict__ adj,
                     const float* __restrict__ W1, const float* __restrict__ b1,
                     const float* __restrict__ W2, const float* __restrict__ b2,
                     const float* __restrict__ g1, const float* __restrict__ be1,
                     const float* __restrict__ m1, const float* __restrict__ v1,
                     const float* __restrict__ g2, const float* __restrict__ be2,
                     const float* __restrict__ m2, const float* __restrict__ v2,
                     float* __restrict__ out, int nsamples)
{
    // lane word-stride 42 (10 mod 32) -> LDS.64 conflict-free per phase
    __shared__ alignas(16) float xs [SPB * HDIM];   // staged X (kept intact)
    __shared__ alignas(16) float s2s[SPB * HDIM];   // S2 scratch
    __shared__ alignas(16) ulonglong2 cap[32];  // packed W1' column pair
    __shared__ alignas(16) ulonglong2 cbp[32];  // packed (W2'/2) row pair
    __shared__ ull ccp[32];                     // packed beta1' pair
    __shared__ ull adjp[NJ * 6];                // packed (a,a)
    __shared__ ull beta2p;

    const int tid  = threadIdx.x;
    const int w    = tid >> 5;          // warp -> joint triple
    const int lane = tid & 31;          // sample slot
    const long long base  = (long long)blockIdx.x * (SPB * HDIM);
    const long long total = (long long)nsamples * HDIM;

    // ---- stage X: 1008 float4 over 224 threads ----
    float4* xs4 = (float4*)xs;
    #pragma unroll
    for (int i = tid; i < SPB * HDIM / 4; i += NTHREADS) {
        long long g = base + 4LL * i;
        float4 v = make_float4(0.f, 0.f, 0.f, 0.f);
        if (g < total) v = *(const float4*)(x + g);
        xs4[i] = v;
    }

    // ---- fold BN into pre-packed weight/bias constants ----
    if (tid < 32) {
        int c0 = 2 * tid, c1 = c0 + 1;
        float al0 = g1[c0] * rsqrtf(v1[c0] + BN_EPS);
        float al1 = g1[c1] * rsqrtf(v1[c1] + BN_EPS);
        cap[tid] = make_ulonglong2(pk2(W1[c0] * al0, W1[c1] * al1),
                                   pk2(W1[HIDDEN + c0] * al0, W1[HIDDEN + c1] * al1));
        ccp[tid] = pk2((b1[c0] - m1[c0]) * al0 + be1[c0],
                       (b1[c1] - m1[c1]) * al1 + be1[c1]);
        float a20 = 0.5f * g2[0] * rsqrtf(v2[0] + BN_EPS);   // 1/2 folded for relu trick
        float a21 = 0.5f * g2[1] * rsqrtf(v2[1] + BN_EPS);
        cbp[tid] = make_ulonglong2(pk2(W2[c0 * 2] * a20, W2[c1 * 2] * a20),
                                   pk2(W2[c0 * 2 + 1] * a21, W2[c1 * 2 + 1] * a21));
        if (tid == 0) {
            float b20 = (b2[0] - m2[0]) * (2.0f * a20) + be2[0];
            float b21 = (b2[1] - m2[1]) * (2.0f * a21) + be2[1];
            beta2p = pk2(b20, b21);
        }
    }
    if (tid >= 64 && tid < 64 + NJ * 6) {
        int i = tid - 64;
        int jj = i / 6, ii = i % 6;
        float a = (ii < c_cnt[jj]) ? adj[jj * NJ + c_nbr[i]] : 0.f;
        adjp[i] = pk2(a, a);
    }
    __syncthreads();

    // ---- Y = (A@X)[j] for 3 samples x 3 joints -> compact ypk[9] ----
    // wrist (warp 0, jj 0) has 6 nnz; every other joint <=3 (zero-padded)
    ull ypk[9];
    #pragma unroll
    for (int k = 0; k < 3; ++k) {
        const float* xr = xs + (lane + 32 * k) * HDIM;
        #pragma unroll
        for (int jj = 0; jj < 3; ++jj) {
            const int j = 3 * w + jj;
            ull y = 0ULL;
            if (jj == 0 && w == 0) {           // wrist: 6 neighbors
                #pragma unroll
                for (int q = 0; q < 6; ++q)
                    y = ffma2(adjp[q], *(const ull*)(xr + 2 * c_nbr[q]), y);
            } else {                            // finger joints: <=3 neighbors
                #pragma unroll
                for (int q = 0; q < 3; ++q)
                    y = ffma2(adjp[j * 6 + q], *(const ull*)(xr + 2 * c_nbr[j * 6 + q]), y);
            }
            ypk[k * 3 + jj] = y;
        }
    }

    // ---- fused layer1 (+BN+relu) -> layer2, two register passes (5 + 4) ----
    channel_pass<5, 0>(ypk, cap, ccp, cbp, s2s, lane, w);
    channel_pass<4, 5>(ypk, cap, ccp, cbp, s2s, lane, w);
    __syncthreads();   // S2 complete (xs untouched)

    // ---- out = A @ S2 + beta2' + x, direct scattered STG.64 ----
    const ull b2pk = beta2p;
    #pragma unroll
    for (int k = 0; k < 3; ++k) {
        const int row = (lane + 32 * k) * HDIM;
        const float* sr = s2s + row;
        #pragma unroll
        for (int jj = 0; jj < 3; ++jj) {
            const int j = 3 * w + jj;
            ull o = b2pk;
            if (jj == 0 && w == 0) {
                #pragma unroll
                for (int q = 0; q < 6; ++q)
                    o = ffma2(adjp[q], *(const ull*)(sr + 2 * c_nbr[q]), o);
            } else {
                #pragma unroll
                for (int q = 0; q < 3; ++q)
                    o = ffma2(adjp[j * 6 + q], *(const ull*)(sr + 2 * c_nbr[j * 6 + q]), o);
            }
            o = fadd2(o, *(const ull*)(xs + row + 2 * j));
            long long g = base + row + 2 * j;
            if (g < total) {
                float o0, o1; upk2(o, o0, o1);
                *(float2*)(out + g) = make_float2(o0, o1);
            }
        }
    }
}

extern "C" void kernel_launch(void* const* d_in, const int* in_sizes, int n_in,
                              void* d_out, int out_size) {
    int nsamples = in_sizes[0] / HDIM;
    int grid = (nsamples + SPB - 1) / SPB;   // 342 for 32768 samples
    hand_gcn_kernel<<<grid, NTHREADS>>>(
        (const float*)d_in[0],  (const float*)d_in[1],  (const float*)d_in[2],
        (const float*)d_in[3],  (const float*)d_in[4],  (const float*)d_in[5],
        (const float*)d_in[6],  (const float*)d_in[7],  (const float*)d_in[8],
        (const float*)d_in[9],  (const float*)d_in[10], (const float*)d_in[11],
        (const float*)d_in[12], (const float*)d_in[13],
        (float*)d_out, nsamples);
}

// round 17
// speedup vs baseline: 1.8901x; 1.8901x over previous
#include <cuda_runtime.h>

// HandGraphConvNet fused: 2-layer GCN + BN(eval) + relu + residual, fp32.
//   Y  = A @ X            (sparse A: wrist=6 nnz, all other joints <=3)
//   H  = relu(Y @ W1' + beta1')      (never materialized)
//   S2 = H @ W2'
//   out = A @ S2 + beta2' + x
// R13: small blocks for fine-grained streaming. Block = 3 warps x 32 lanes;
// warp w <-> joints {7w..7w+6}, lane <-> sample, SPB=32 -> 1024 blocks,
// ~6.9/SM => makespan imbalance ~1.2% (vs 15% tail at 512 big blocks).
// 7 units/thread amortize each channel-constant load; launch_bounds(96,6)
// leaves a 113-reg cap (live ~70) so the R12 spill cannot recur.
// Packed relu: relu(h)*w == (h + (h & 0x7fffffff)) * (w/2), 1/2 pre-folded.

#define NJ 21
#define HDIM 42
#define HIDDEN 64
#define SPB 32                 // samples per block (1 per lane)
#define NTHREADS 96            // 3 warps
#define BN_EPS 1e-5f

typedef unsigned long long ull;

__constant__ int c_nbr[NJ * 6] = {
    0,1,5,9,13,17,
    0,1,2,0,0,0, 1,2,3,0,0,0, 2,3,4,0,0,0, 3,4,0,0,0,0,
    0,5,6,0,0,0, 5,6,7,0,0,0, 6,7,8,0,0,0, 7,8,0,0,0,0,
    0,9,10,0,0,0, 9,10,11,0,0,0, 10,11,12,0,0,0, 11,12,0,0,0,0,
    0,13,14,0,0,0, 13,14,15,0,0,0, 14,15,16,0,0,0, 15,16,0,0,0,0,
    0,17,18,0,0,0, 17,18,19,0,0,0, 18,19,20,0,0,0, 19,20,0,0,0,0};
__constant__ int c_cnt[NJ] = {6,3,3,3,2,3,3,3,2,3,3,3,2,3,3,3,2,3,3,3,2};

__device__ __forceinline__ ull pk2(float lo, float hi) {
    ull r; asm("mov.b64 %0, {%1, %2};" : "=l"(r) : "f"(lo), "f"(hi)); return r;
}
__device__ __forceinline__ void upk2(ull v, float& lo, float& hi) {
    asm("mov.b64 {%0, %1}, %2;" : "=f"(lo), "=f"(hi) : "l"(v));
}
__device__ __forceinline__ ull ffma2(ull a, ull b, ull c) {
    ull d; asm("fma.rn.f32x2 %0, %1, %2, %3;" : "=l"(d) : "l"(a), "l"(b), "l"(c)); return d;
}
__device__ __forceinline__ ull fadd2(ull a, ull b) {
    ull d; asm("add.rn.f32x2 %0, %1, %2;" : "=l"(d) : "l"(a), "l"(b)); return d;
}

__global__ __launch_bounds__(NTHREADS, 6)
void hand_gcn_kernel(const float* __restrict__ x,  const float* __restrict__ adj,
                     const float* __restrict__ W1, const float* __restrict__ b1,
                     const float* __restrict__ W2, const float* __restrict__ b2,
                     const float* __restrict__ g1, const float* __restrict__ be1,
                     const float* __restrict__ m1, const float* __restrict__ v1,
                     const float* __restrict__ g2, const float* __restrict__ be2,
                     const float* __restrict__ m2, const float* __restrict__ v2,
                     float* __restrict__ out, int nsamples)
{
    // lane word-stride 42 (10 mod 32) -> LDS.64 conflict-free per phase
    __shared__ alignas(16) float xs [SPB * HDIM];   // staged X (kept intact)
    __shared__ alignas(16) float s2s[SPB * HDIM];   // S2 scratch
    __shared__ alignas(16) ulonglong2 cap[32];  // packed W1' column pair
    __shared__ alignas(16) ulonglong2 cbp[32];  // packed (W2'/2) row pair
    __shared__ ull ccp[32];                     // packed beta1' pair
    __shared__ ull adjp[NJ * 6];                // packed (a,a)
    __shared__ ull beta2p;

    const int tid  = threadIdx.x;
    const int w    = tid >> 5;          // warp -> 7-joint group
    const int lane = tid & 31;          // sample slot
    const long long base  = (long long)blockIdx.x * (SPB * HDIM);
    const long long total = (long long)nsamples * HDIM;

    // ---- stage X: 336 float4 over 96 threads ----
    float4* xs4 = (float4*)xs;
    #pragma unroll
    for (int i = tid; i < SPB * HDIM / 4; i += NTHREADS) {
        long long g = base + 4LL * i;
        float4 v = make_float4(0.f, 0.f, 0.f, 0.f);
        if (g < total) v = *(const float4*)(x + g);
        xs4[i] = v;
    }

    // ---- fold BN into pre-packed weight/bias constants ----
    if (tid < 32) {
        int c0 = 2 * tid, c1 = c0 + 1;
        float al0 = g1[c0] * rsqrtf(v1[c0] + BN_EPS);
        float al1 = g1[c1] * rsqrtf(v1[c1] + BN_EPS);
        cap[tid] = make_ulonglong2(pk2(W1[c0] * al0, W1[c1] * al1),
                                   pk2(W1[HIDDEN + c0] * al0, W1[HIDDEN + c1] * al1));
        ccp[tid] = pk2((b1[c0] - m1[c0]) * al0 + be1[c0],
                       (b1[c1] - m1[c1]) * al1 + be1[c1]);
        float a20 = 0.5f * g2[0] * rsqrtf(v2[0] + BN_EPS);   // 1/2 folded for relu trick
        float a21 = 0.5f * g2[1] * rsqrtf(v2[1] + BN_EPS);
        cbp[tid] = make_ulonglong2(pk2(W2[c0 * 2] * a20, W2[c1 * 2] * a20),
                                   pk2(W2[c0 * 2 + 1] * a21, W2[c1 * 2 + 1] * a21));
        if (tid == 0) {
            float b20 = (b2[0] - m2[0]) * (2.0f * a20) + be2[0];
            float b21 = (b2[1] - m2[1]) * (2.0f * a21) + be2[1];
            beta2p = pk2(b20, b21);
        }
    }
    #pragma unroll
    for (int i = tid; i < NJ * 6; i += NTHREADS) {
        int jj = i / 6, ii = i % 6;
        float a = (ii < c_cnt[jj]) ? adj[jj * NJ + c_nbr[i]] : 0.f;
        adjp[i] = pk2(a, a);
    }
    __syncthreads();

    // ---- Y = (A@X)[j] for this lane's sample, 7 joints -> splat halves ----
    // wrist (warp 0, jj 0) has 6 nnz; every other joint <=3 (zero-padded)
    const float* xr = xs + lane * HDIM;
    ull y0d[7], y1d[7];
    #pragma unroll
    for (int jj = 0; jj < 7; ++jj) {
        const int j = 7 * w + jj;
        ull y = 0ULL;
        if (jj == 0 && w == 0) {           // wrist: 6 neighbors
            #pragma unroll
            for (int q = 0; q < 6; ++q)
                y = ffma2(adjp[q], *(const ull*)(xr + 2 * c_nbr[q]), y);
        } else {                            // finger joints: <=3 neighbors
            #pragma unroll
            for (int q = 0; q < 3; ++q)
                y = ffma2(adjp[j * 6 + q], *(const ull*)(xr + 2 * c_nbr[j * 6 + q]), y);
        }
        float y0, y1; upk2(y, y0, y1);
        y0d[jj] = pk2(y0, y0);
        y1d[jj] = pk2(y1, y1);
    }

    // ---- fused layer1 (+BN+relu) -> layer2 contraction, 7 units/thread ----
    const ull ABSMASK = 0x7FFFFFFF7FFFFFFFULL;
    ull a0[7], a1[7];
    #pragma unroll
    for (int t = 0; t < 7; ++t) { a0[t] = 0ULL; a1[t] = 0ULL; }
    #pragma unroll
    for (int cp = 0; cp < 32; ++cp) {
        ulonglong2 wa = cap[cp];      // LDS.128 broadcast
        ull        bp = ccp[cp];      // LDS.64
        ulonglong2 wb = cbp[cp];      // LDS.128 (pre-scaled by 1/2)
        #pragma unroll
        for (int t = 0; t < 7; ++t) {
            ull h  = ffma2(y0d[t], wa.x, ffma2(y1d[t], wa.y, bp));
            ull hr = fadd2(h, h & ABSMASK);        // 2*relu(h), packed
            a0[t] = ffma2(hr, wb.x, a0[t]);
            a1[t] = ffma2(hr, wb.y, a1[t]);
        }
    }
    float* srow = s2s + lane * HDIM;
    #pragma unroll
    for (int jj = 0; jj < 7; ++jj) {
        float p, q, r, s;
        upk2(a0[jj], p, q);
        upk2(a1[jj], r, s);
        *(float2*)(srow + 2 * (7 * w + jj)) = make_float2(p + q, r + s);
    }
    __syncthreads();   // S2 complete (xs untouched)

    // ---- out = A @ S2 + beta2' + x, direct scattered STG.64 ----
    const ull b2pk = beta2p;
    #pragma unroll
    for (int jj = 0; jj < 7; ++jj) {
        const int j = 7 * w + jj;
        ull o = b2pk;
        if (jj == 0 && w == 0) {
            #pragma unroll
            for (int q = 0; q < 6; ++q)
                o = ffma2(adjp[q], *(const ull*)(srow + 2 * c_nbr[q]), o);
        } else {
            #pragma unroll
            for (int q = 0; q < 3; ++q)
                o = ffma2(adjp[j * 6 + q], *(const ull*)(srow + 2 * c_nbr[j * 6 + q]), o);
        }
        o = fadd2(o, *(const ull*)(xr + 2 * j));
        long long g = base + lane * HDIM + 2 * j;
        if (g < total) {
            float o0, o1; upk2(o, o0, o1);
            *(float2*)(out + g) = make_float2(o0, o1);
        }
    }
}

extern "C" void kernel_launch(void* const* d_in, const int* in_sizes, int n_in,
                              void* d_out, int out_size) {
    int nsamples = in_sizes[0] / HDIM;
    int grid = (nsamples + SPB - 1) / SPB;   // 1024 for 32768 samples
    hand_gcn_kernel<<<grid, NTHREADS>>>(
        (const float*)d_in[0],  (const float*)d_in[1],  (const float*)d_in[2],
        (const float*)d_in[3],  (const float*)d_in[4],  (const float*)d_in[5],
        (const float*)d_in[6],  (const float*)d_in[7],  (const float*)d_in[8],
        (const float*)d_in[9],  (const float*)d_in[10], (const float*)d_in[11],
        (const float*)d_in[12], (const float*)d_in[13],
        (float*)d_out, nsamples);
}